// round 9
// baseline (speedup 1.0000x reference)
#include <cuda_runtime.h>
#include <cstdint>

// Problem constants
#define BATCH 8
#define HH 384
#define WW 384
#define PHI 32
#define RHO 64
#define Q_SCALE (255.0f / 32.0f)

// Tiling: persistent blocks loop over small tiles
#define TY 4
#define TX 128
#define TILES_X (WW / TX)           // 3
#define TILES_Y (HH / TY)           // 96
#define NTILES (TILES_X * TILES_Y * BATCH)   // 2304
#define GRID_BLOCKS 444             // 148 SMs x 3 CTAs

// ---------------------------------------------------------------------------
// f32x2 packed helpers (sm_103a)
// ---------------------------------------------------------------------------
__device__ __forceinline__ unsigned long long ffma2(unsigned long long a,
                                                    unsigned long long b,
                                                    unsigned long long c) {
    unsigned long long d;
    asm("fma.rn.f32x2 %0, %1, %2, %3;" : "=l"(d) : "l"(a), "l"(b), "l"(c));
    return d;
}
__device__ __forceinline__ unsigned long long pack_dup(float v) {
    unsigned long long d;
    asm("mov.b64 %0, {%1, %1};" : "=l"(d) : "f"(v));
    return d;
}
__device__ __forceinline__ unsigned long long pack2(float lo, float hi) {
    unsigned long long d;
    asm("mov.b64 %0, {%1, %2};" : "=l"(d) : "f"(lo), "f"(hi));
    return d;
}
__device__ __forceinline__ void unpack2(unsigned long long a, float& lo, float& hi) {
    asm("mov.b64 {%0, %1}, %2;" : "=f"(lo), "=f"(hi) : "l"(a));
}

// ---------------------------------------------------------------------------
// Persistent fused kernel. Math recap:
//   q = floor(x*255/32) in {0..7}; MLP collapses to 8x64 LUT
//   u[l][c] = ((relu(l*w1+b1) @ w2 + b2) @ w3) / 9.
//   out[c] = relu( sum_{l=1..7} n_l*(u[l][c]-u[0][c]) + (b3[c]+9*u[0][c]) )
//   Count->float: bits (n | 0x4B000000) = 2^23 + n, subtract 2^23 (exact).
// LUT computed ONCE per block; block then loops tiles with static stride.
// ---------------------------------------------------------------------------
__global__ __launch_bounds__(256, 3)
void lpmp_fused(const float* __restrict__ x,
                const float* __restrict__ w1, const float* __restrict__ b1,
                const float* __restrict__ w2, const float* __restrict__ b2,
                const float* __restrict__ w3, const float* __restrict__ b3,
                float* __restrict__ out) {
    __shared__ float h2S[8][PHI];            // hidden layer per level (prelude only)
    __shared__ float uRaw[8][RHO];           // raw LUT (prelude only)
    __shared__ float uS[7][RHO];             // u[l]-u[0]
    __shared__ float biasS[RHO];             // b3 + 9*u[0]
    __shared__ uint32_t oneS[TY + 2][TX + 4]; // per-pixel one-hot words (x-halo at 0 / TX+1)
    __shared__ uint32_t rs[TY + 2][TX];      // horizontal 3-sums
    __shared__ uint32_t pk[TY][TX];          // 3x3 packed nibble counts

    const int tid = threadIdx.y * 32 + threadIdx.x;

    // ======================= Prelude (once per block) =======================
    // Phase 0a: h2[l][d] = b2[d] + sum_j relu(l*w1[j]+b1[j]) * w2[j][d]
    {
        int l = tid >> 5;            // 0..7
        int d = tid & 31;            // 0..31
        float acc = b2[d];
        float lf = (float)l;
#pragma unroll
        for (int j = 0; j < PHI; j++) {
            float h1 = fmaxf(fmaf(lf, w1[j], b1[j]), 0.0f);
            acc = fmaf(h1, w2[j * PHI + d], acc);
        }
        h2S[l][d] = acc;
    }
    __syncthreads();

    // Phase 0b: uRaw[l][c] = (h2[l] . w3[:,c]) / 9
#pragma unroll
    for (int e = 0; e < 2; e++) {
        int idx = tid + e * 256;
        int l = idx >> 6;
        int c = idx & 63;
        float acc = 0.0f;
#pragma unroll
        for (int d = 0; d < PHI; d++)
            acc = fmaf(h2S[l][d], w3[d * RHO + c], acc);
        uRaw[l][c] = acc * (1.0f / 9.0f);
    }
    __syncthreads();

    // Phase 0c: diff LUT + bias
#pragma unroll
    for (int e = 0; e < 2; e++) {
        int idx = tid + e * 256;
        if (idx < 448) {
            int l = idx >> 6;        // 0..6 -> level l+1
            int c = idx & 63;
            uS[l][c] = uRaw[l + 1][c] - uRaw[0][c];
        } else {
            int c = idx - 448;
            biasS[c] = fmaf(9.0f, uRaw[0][c], b3[c]);
        }
    }
    __syncthreads();

    // Per-warp channel slice: warp = 8 channels, lane = x-quad (R8 geometry)
    const int cg = threadIdx.y;
    const int q  = threadIdx.x;
    const int c8 = cg * 8;
    unsigned long long B2[4];
#pragma unroll
    for (int p = 0; p < 4; p++) {
        const float2 bv = *reinterpret_cast<const float2*>(&biasS[c8 + 2 * p]);
        B2[p] = pack2(bv.x, bv.y);
    }
    const size_t plane = (size_t)HH * WW;

    // ========================== Tile loop ==========================
    for (int t = blockIdx.x; t < NTILES; t += GRID_BLOCKS) {
        const int txi = t % TILES_X;
        const int tmp = t / TILES_X;
        const int tyi = tmp % TILES_Y;
        const int b   = tmp / TILES_Y;
        const int x0  = txi * TX;
        const int y0  = tyi * TY;
        const float* xb = x + (size_t)b * HH * WW;

        // ---- Stage A0: one-hot word per pixel (rows y0-1..y0+TY, cols x0-1..x0+TX) ----
        // Safe vs. previous tile's stage B (which reads only pk).
        for (int idx = tid; idx < (TY + 2) * (TX + 2); idx += 256) {
            int r  = idx / (TX + 2);          // 0..TY+1
            int xi = idx - r * (TX + 2);      // 0..TX+1
            int yg = y0 - 1 + r;
            int xg = x0 - 1 + xi;
            uint32_t s;
            if (yg < 0 || yg >= HH || xg < 0 || xg >= WW) {
                s = 1u;                       // zero-pad -> level 0
            } else {
                s = 1u << (4 * (int)(xb[(size_t)yg * WW + xg] * Q_SCALE));
            }
            oneS[r][xi] = s;
        }
        __syncthreads();

        // ---- Stage A1: horizontal 3-sums ----
        for (int idx = tid; idx < (TY + 2) * TX; idx += 256) {
            int r  = idx / TX;
            int xi = idx - r * TX;
            rs[r][xi] = oneS[r][xi] + oneS[r][xi + 1] + oneS[r][xi + 2];
        }
        __syncthreads();   // also guarantees prev-tile stage B fully done (pk safe)

        // ---- Stage A2: vertical 3-sums -> packed counts ----
        for (int idx = tid; idx < TY * TX; idx += 256) {
            int r  = idx / TX;
            int xi = idx - r * TX;
            pk[r][xi] = rs[r][xi] + rs[r + 1][xi] + rs[r + 2][xi];
        }
        __syncthreads();

        // ---- Stage B: levels-outer, LUT streamed from SMEM (broadcast LDS) ----
        const int xbase = x0 + 4 * q;
        float* obase = out + ((size_t)(b * RHO + c8) * HH + y0) * WW + xbase;

#pragma unroll 1
        for (int ty = 0; ty < TY; ty++) {
            uint32_t pv[4];
#pragma unroll
            for (int i = 0; i < 4; i++)
                pv[i] = pk[ty][4 * q + i];

            unsigned long long acc[4][4];   // [pixel][pair]
#pragma unroll
            for (int l = 0; l < 7; l++) {
                unsigned long long Ul[4];
#pragma unroll
                for (int p = 0; p < 4; p++) {
                    const float2 uv = *reinterpret_cast<const float2*>(&uS[l][c8 + 2 * p]);
                    Ul[p] = pack2(uv.x, uv.y);
                }
#pragma unroll
                for (int i = 0; i < 4; i++) {
                    uint32_t bits = ((pv[i] >> (4 * (l + 1))) & 0xFu) | 0x4B000000u;
                    unsigned long long md = pack_dup(__uint_as_float(bits) - 8388608.0f);
                    if (l == 0) {
#pragma unroll
                        for (int p = 0; p < 4; p++)
                            acc[i][p] = ffma2(md, Ul[p], B2[p]);
                    } else {
#pragma unroll
                        for (int p = 0; p < 4; p++)
                            acc[i][p] = ffma2(md, Ul[p], acc[i][p]);
                    }
                }
            }

            // ReLU + streaming float4 stores: 512B contiguous per warp per plane-row
            float* orow = obase + (size_t)ty * WW;
#pragma unroll
            for (int p = 0; p < 4; p++) {
                float lo0, hi0, lo1, hi1, lo2, hi2, lo3, hi3;
                unpack2(acc[0][p], lo0, hi0);
                unpack2(acc[1][p], lo1, hi1);
                unpack2(acc[2][p], lo2, hi2);
                unpack2(acc[3][p], lo3, hi3);
                float4 v0 = make_float4(fmaxf(lo0, 0.0f), fmaxf(lo1, 0.0f),
                                        fmaxf(lo2, 0.0f), fmaxf(lo3, 0.0f));
                float4 v1 = make_float4(fmaxf(hi0, 0.0f), fmaxf(hi1, 0.0f),
                                        fmaxf(hi2, 0.0f), fmaxf(hi3, 0.0f));
                __stcs(reinterpret_cast<float4*>(orow + (size_t)(2 * p) * plane), v0);
                __stcs(reinterpret_cast<float4*>(orow + (size_t)(2 * p + 1) * plane), v1);
            }
        }
        // no sync here: next iteration's oneS/rs writes don't touch pk until after a sync
    }
}

// ---------------------------------------------------------------------------
// Harness entry point
// ---------------------------------------------------------------------------
extern "C" void kernel_launch(void* const* d_in, const int* in_sizes, int n_in,
                              void* d_out, int out_size) {
    const float* x  = (const float*)d_in[0];
    const float* w1 = (const float*)d_in[1];
    const float* b1 = (const float*)d_in[2];
    const float* w2 = (const float*)d_in[3];
    const float* b2 = (const float*)d_in[4];
    const float* w3 = (const float*)d_in[5];
    const float* b3 = (const float*)d_in[6];
    float* out = (float*)d_out;

    dim3 blk(32, 8);
    lpmp_fused<<<GRID_BLOCKS, blk>>>(x, w1, b1, w2, b2, w3, b3, out);
}

// round 10
// speedup vs baseline: 1.0132x; 1.0132x over previous
#include <cuda_runtime.h>
#include <cstdint>

// Problem constants
#define BATCH 8
#define HH 384
#define WW 384
#define PHI 32
#define RHO 64
#define Q_SCALE (255.0f / 32.0f)

#define TY 8
#define TX 128
#define ONE_W (TX + 4)     // oneS row stride (130 used, padded to 132)

// ---------------------------------------------------------------------------
// f32x2 packed helpers (sm_103a)
// ---------------------------------------------------------------------------
__device__ __forceinline__ unsigned long long ffma2(unsigned long long a,
                                                    unsigned long long b,
                                                    unsigned long long c) {
    unsigned long long d;
    asm("fma.rn.f32x2 %0, %1, %2, %3;" : "=l"(d) : "l"(a), "l"(b), "l"(c));
    return d;
}
__device__ __forceinline__ unsigned long long pack_dup(float v) {
    unsigned long long d;
    asm("mov.b64 %0, {%1, %1};" : "=l"(d) : "f"(v));
    return d;
}
__device__ __forceinline__ unsigned long long pack2(float lo, float hi) {
    unsigned long long d;
    asm("mov.b64 %0, {%1, %2};" : "=l"(d) : "f"(lo), "f"(hi));
    return d;
}
__device__ __forceinline__ void unpack2(unsigned long long a, float& lo, float& hi) {
    asm("mov.b64 {%0, %1}, %2;" : "=f"(lo), "=f"(hi) : "l"(a));
}

// ---------------------------------------------------------------------------
// Fused kernel (R8 base + single-F2I merged stage A).
//   q = floor(x*255/32) in {0..7}; MLP collapses to 8x64 LUT
//   u[l][c] = ((relu(l*w1+b1) @ w2 + b2) @ w3) / 9.
//   out[c] = relu( sum_{l=1..7} n_l*(u[l][c]-u[0][c]) + (b3[c]+9*u[0][c]) )
//   Count->float: bits (n | 0x4B000000) = 2^23 + n, subtract 2^23 (exact).
// Stage A: ONE float->int conversion per pixel (incl. halo) into a one-hot
// nibble word, then a single merged 3x3 sum pass -> packed counts.
// Stage B: levels-outer FFMA2, LUT broadcast from SMEM; warp = 8 channels,
// lane = x-quad -> every STG.128 is 512B contiguous per warp.
// ---------------------------------------------------------------------------
__global__ __launch_bounds__(256, 3)
void lpmp_fused(const float* __restrict__ x,
                const float* __restrict__ w1, const float* __restrict__ b1,
                const float* __restrict__ w2, const float* __restrict__ b2,
                const float* __restrict__ w3, const float* __restrict__ b3,
                float* __restrict__ out) {
    __shared__ float h2S[8][PHI];           // hidden layer per level
    __shared__ float uRaw[8][RHO];          // raw LUT
    __shared__ float uS[7][RHO];            // u[l]-u[0]
    __shared__ float biasS[RHO];            // b3 + 9*u[0]
    __shared__ uint32_t oneS[TY + 2][ONE_W]; // per-pixel one-hot words (x-halo at col 0 / TX+1)
    __shared__ uint32_t pk[TY][TX];         // 3x3 packed nibble counts

    const int x0 = blockIdx.x * TX;
    const int y0 = blockIdx.y * TY;
    const int b  = blockIdx.z;
    const int tid = threadIdx.y * 32 + threadIdx.x;
    const float* xb = x + (size_t)b * HH * WW;

    // ---- Phase 0a: h2[l][d] = b2[d] + sum_j relu(l*w1[j]+b1[j]) * w2[j][d] ----
    {
        int l = tid >> 5;            // 0..7
        int d = tid & 31;            // 0..31
        float acc = b2[d];
        float lf = (float)l;
#pragma unroll
        for (int j = 0; j < PHI; j++) {
            float h1 = fmaxf(fmaf(lf, w1[j], b1[j]), 0.0f);
            acc = fmaf(h1, w2[j * PHI + d], acc);
        }
        h2S[l][d] = acc;
    }
    __syncthreads();

    // ---- Phase 0b: uRaw[l][c] = (h2[l] . w3[:,c]) / 9, 512 entries ----
#pragma unroll
    for (int e = 0; e < 2; e++) {
        int idx = tid + e * 256;
        int l = idx >> 6;
        int c = idx & 63;
        float acc = 0.0f;
#pragma unroll
        for (int d = 0; d < PHI; d++)
            acc = fmaf(h2S[l][d], w3[d * RHO + c], acc);
        uRaw[l][c] = acc * (1.0f / 9.0f);
    }
    __syncthreads();

    // ---- Phase 0c: diff LUT + bias; Stage A0: one-hot word per pixel ----
    {
#pragma unroll
        for (int e = 0; e < 2; e++) {
            int idx = tid + e * 256;
            if (idx < 448) {
                int l = idx >> 6;        // 0..6 -> level l+1
                int c = idx & 63;
                uS[l][c] = uRaw[l + 1][c] - uRaw[0][c];
            } else {
                int c = idx - 448;
                biasS[c] = fmaf(9.0f, uRaw[0][c], b3[c]);
            }
        }
        // Stage A0: rows y0-1..y0+TY, cols x0-1..x0+TX -> one F2I per pixel
        for (int idx = tid; idx < (TY + 2) * (TX + 2); idx += 256) {
            int r  = idx / (TX + 2);          // 0..TY+1
            int xi = idx - r * (TX + 2);      // 0..TX+1
            int yg = y0 - 1 + r;
            int xg = x0 - 1 + xi;
            uint32_t s;
            if (yg < 0 || yg >= HH || xg < 0 || xg >= WW) {
                s = 1u;                       // zero-pad -> level 0
            } else {
                s = 1u << (4 * (int)(xb[(size_t)yg * WW + xg] * Q_SCALE));
            }
            oneS[r][xi] = s;
        }
    }
    __syncthreads();

    // ---- Stage A (merged): 3x3 sum of one-hot words -> packed counts ----
    for (int idx = tid; idx < TY * TX; idx += 256) {
        int r  = idx / TX;                    // output row in tile
        int xi = idx - r * TX;                // output col in tile
        uint32_t s0 = oneS[r][xi]     + oneS[r][xi + 1]     + oneS[r][xi + 2];
        uint32_t s1 = oneS[r + 1][xi] + oneS[r + 1][xi + 1] + oneS[r + 1][xi + 2];
        uint32_t s2 = oneS[r + 2][xi] + oneS[r + 2][xi + 1] + oneS[r + 2][xi + 2];
        pk[r][xi] = s0 + s1 + s2;
    }

    // ---- Stage B setup: warp = 8 channels, lane = x-quad ----
    const int cg = threadIdx.y;
    const int q  = threadIdx.x;
    const int c8 = cg * 8;

    unsigned long long B2[4];
#pragma unroll
    for (int p = 0; p < 4; p++) {
        const float2 bv = *reinterpret_cast<const float2*>(&biasS[c8 + 2 * p]);
        B2[p] = pack2(bv.x, bv.y);
    }
    __syncthreads();   // pk ready

    const int xbase = x0 + 4 * q;
    float* obase = out + ((size_t)(b * RHO + c8) * HH + y0) * WW + xbase;
    const size_t plane = (size_t)HH * WW;

    // ---- Stage B: levels-outer, LUT streamed from SMEM (broadcast LDS) ----
#pragma unroll 1
    for (int ty = 0; ty < TY; ty++) {
        uint32_t pv[4];
#pragma unroll
        for (int i = 0; i < 4; i++)
            pv[i] = pk[ty][4 * q + i];

        unsigned long long acc[4][4];   // [pixel][pair]
#pragma unroll
        for (int l = 0; l < 7; l++) {
            unsigned long long Ul[4];
#pragma unroll
            for (int p = 0; p < 4; p++) {
                const float2 uv = *reinterpret_cast<const float2*>(&uS[l][c8 + 2 * p]);
                Ul[p] = pack2(uv.x, uv.y);
            }
#pragma unroll
            for (int i = 0; i < 4; i++) {
                uint32_t bits = ((pv[i] >> (4 * (l + 1))) & 0xFu) | 0x4B000000u;
                unsigned long long md = pack_dup(__uint_as_float(bits) - 8388608.0f);
                if (l == 0) {
#pragma unroll
                    for (int p = 0; p < 4; p++)
                        acc[i][p] = ffma2(md, Ul[p], B2[p]);
                } else {
#pragma unroll
                    for (int p = 0; p < 4; p++)
                        acc[i][p] = ffma2(md, Ul[p], acc[i][p]);
                }
            }
        }

        // ReLU + streaming float4 stores: 512B contiguous per warp per plane-row
        float* orow = obase + (size_t)ty * WW;
#pragma unroll
        for (int p = 0; p < 4; p++) {
            float lo0, hi0, lo1, hi1, lo2, hi2, lo3, hi3;
            unpack2(acc[0][p], lo0, hi0);
            unpack2(acc[1][p], lo1, hi1);
            unpack2(acc[2][p], lo2, hi2);
            unpack2(acc[3][p], lo3, hi3);
            float4 v0 = make_float4(fmaxf(lo0, 0.0f), fmaxf(lo1, 0.0f),
                                    fmaxf(lo2, 0.0f), fmaxf(lo3, 0.0f));
            float4 v1 = make_float4(fmaxf(hi0, 0.0f), fmaxf(hi1, 0.0f),
                                    fmaxf(hi2, 0.0f), fmaxf(hi3, 0.0f));
            __stcs(reinterpret_cast<float4*>(orow + (size_t)(2 * p) * plane), v0);
            __stcs(reinterpret_cast<float4*>(orow + (size_t)(2 * p + 1) * plane), v1);
        }
    }
}

// ---------------------------------------------------------------------------
// Harness entry point
// ---------------------------------------------------------------------------
extern "C" void kernel_launch(void* const* d_in, const int* in_sizes, int n_in,
                              void* d_out, int out_size) {
    const float* x  = (const float*)d_in[0];
    const float* w1 = (const float*)d_in[1];
    const float* b1 = (const float*)d_in[2];
    const float* w2 = (const float*)d_in[3];
    const float* b2 = (const float*)d_in[4];
    const float* w3 = (const float*)d_in[5];
    const float* b3 = (const float*)d_in[6];
    float* out = (float*)d_out;

    dim3 grid(WW / TX, HH / TY, BATCH);   // (3, 48, 8) = 1152 blocks
    dim3 blk(32, 8);
    lpmp_fused<<<grid, blk>>>(x, w1, b1, w2, b2, w3, b3, out);
}

// round 11
// speedup vs baseline: 1.0138x; 1.0006x over previous
#include <cuda_runtime.h>
#include <cstdint>

// Problem constants
#define BATCH 8
#define HH 384
#define WW 384
#define PHI 32
#define RHO 64
#define Q_SCALE (255.0f / 32.0f)

#define TY 8
#define TX 128
#define ONE_W (TX + 4)     // oneS row stride (130 used, padded)

// ---------------------------------------------------------------------------
// f32x2 packed helpers (sm_103a)
// ---------------------------------------------------------------------------
__device__ __forceinline__ unsigned long long ffma2(unsigned long long a,
                                                    unsigned long long b,
                                                    unsigned long long c) {
    unsigned long long d;
    asm("fma.rn.f32x2 %0, %1, %2, %3;" : "=l"(d) : "l"(a), "l"(b), "l"(c));
    return d;
}
__device__ __forceinline__ unsigned long long pack_dup(float v) {
    unsigned long long d;
    asm("mov.b64 %0, {%1, %1};" : "=l"(d) : "f"(v));
    return d;
}
__device__ __forceinline__ unsigned long long pack2(float lo, float hi) {
    unsigned long long d;
    asm("mov.b64 %0, {%1, %2};" : "=l"(d) : "f"(lo), "f"(hi));
    return d;
}
__device__ __forceinline__ void unpack2(unsigned long long a, float& lo, float& hi) {
    asm("mov.b64 {%0, %1}, %2;" : "=f"(lo), "=f"(hi) : "l"(a));
}

// ---------------------------------------------------------------------------
// Fused kernel (R8 champion + single-F2I one-hot stage + separable sums).
//   q = floor(x*255/32) in {0..7}; MLP collapses to 8x64 LUT
//   u[l][c] = ((relu(l*w1+b1) @ w2 + b2) @ w3) / 9.
//   out[c] = relu( sum_{l=1..7} n_l*(u[l][c]-u[0][c]) + (b3[c]+9*u[0][c]) )
//   Count->float: bits (n | 0x4B000000) = 2^23 + n, subtract 2^23 (exact).
// Stage A0: ONE float->int conversion per pixel (incl. halo) -> one-hot word.
// Stage A1: horizontal 3-sum (3 LDS).  Stage A2: vertical 3-sum (3 LDS).
// Stage B: levels-outer FFMA2, LUT broadcast from SMEM; warp = 8 channels,
// lane = x-quad -> every STG.128 is 512B contiguous per warp.
// ---------------------------------------------------------------------------
__global__ __launch_bounds__(256, 3)
void lpmp_fused(const float* __restrict__ x,
                const float* __restrict__ w1, const float* __restrict__ b1,
                const float* __restrict__ w2, const float* __restrict__ b2,
                const float* __restrict__ w3, const float* __restrict__ b3,
                float* __restrict__ out) {
    __shared__ float h2S[8][PHI];            // hidden layer per level
    __shared__ float uRaw[8][RHO];           // raw LUT
    __shared__ float uS[7][RHO];             // u[l]-u[0]
    __shared__ float biasS[RHO];             // b3 + 9*u[0]
    __shared__ uint32_t oneS[TY + 2][ONE_W]; // per-pixel one-hot words (x-halo col 0 / TX+1)
    __shared__ uint32_t rs[TY + 2][TX];      // horizontal 3-sums
    __shared__ uint32_t pk[TY][TX];          // 3x3 packed nibble counts

    const int x0 = blockIdx.x * TX;
    const int y0 = blockIdx.y * TY;
    const int b  = blockIdx.z;
    const int tid = threadIdx.y * 32 + threadIdx.x;
    const float* xb = x + (size_t)b * HH * WW;

    // ---- Phase 0a: h2[l][d] = b2[d] + sum_j relu(l*w1[j]+b1[j]) * w2[j][d] ----
    {
        int l = tid >> 5;            // 0..7
        int d = tid & 31;            // 0..31
        float acc = b2[d];
        float lf = (float)l;
#pragma unroll
        for (int j = 0; j < PHI; j++) {
            float h1 = fmaxf(fmaf(lf, w1[j], b1[j]), 0.0f);
            acc = fmaf(h1, w2[j * PHI + d], acc);
        }
        h2S[l][d] = acc;
    }
    __syncthreads();

    // ---- Phase 0b: uRaw[l][c] = (h2[l] . w3[:,c]) / 9, 512 entries ----
#pragma unroll
    for (int e = 0; e < 2; e++) {
        int idx = tid + e * 256;
        int l = idx >> 6;
        int c = idx & 63;
        float acc = 0.0f;
#pragma unroll
        for (int d = 0; d < PHI; d++)
            acc = fmaf(h2S[l][d], w3[d * RHO + c], acc);
        uRaw[l][c] = acc * (1.0f / 9.0f);
    }
    __syncthreads();

    // ---- Phase 0c: diff LUT + bias; Stage A0: one-hot word per pixel ----
    {
#pragma unroll
        for (int e = 0; e < 2; e++) {
            int idx = tid + e * 256;
            if (idx < 448) {
                int l = idx >> 6;        // 0..6 -> level l+1
                int c = idx & 63;
                uS[l][c] = uRaw[l + 1][c] - uRaw[0][c];
            } else {
                int c = idx - 448;
                biasS[c] = fmaf(9.0f, uRaw[0][c], b3[c]);
            }
        }
        // Stage A0: rows y0-1..y0+TY, cols x0-1..x0+TX -> one F2I per pixel
        for (int idx = tid; idx < (TY + 2) * (TX + 2); idx += 256) {
            int r  = idx / (TX + 2);          // 0..TY+1
            int xi = idx - r * (TX + 2);      // 0..TX+1
            int yg = y0 - 1 + r;
            int xg = x0 - 1 + xi;
            uint32_t s;
            if (yg < 0 || yg >= HH || xg < 0 || xg >= WW) {
                s = 1u;                       // zero-pad -> level 0
            } else {
                s = 1u << (4 * (int)(xb[(size_t)yg * WW + xg] * Q_SCALE));
            }
            oneS[r][xi] = s;
        }
    }
    __syncthreads();

    // ---- Stage A1: horizontal 3-sums (3 LDS each) ----
    for (int idx = tid; idx < (TY + 2) * TX; idx += 256) {
        int r  = idx / TX;
        int xi = idx - r * TX;
        rs[r][xi] = oneS[r][xi] + oneS[r][xi + 1] + oneS[r][xi + 2];
    }
    __syncthreads();

    // ---- Stage A2: vertical 3-sums -> packed counts (3 LDS each) ----
    for (int idx = tid; idx < TY * TX; idx += 256) {
        int r  = idx / TX;
        int xi = idx - r * TX;
        pk[r][xi] = rs[r][xi] + rs[r + 1][xi] + rs[r + 2][xi];
    }

    // ---- Stage B setup: warp = 8 channels, lane = x-quad ----
    const int cg = threadIdx.y;
    const int q  = threadIdx.x;
    const int c8 = cg * 8;

    unsigned long long B2[4];
#pragma unroll
    for (int p = 0; p < 4; p++) {
        const float2 bv = *reinterpret_cast<const float2*>(&biasS[c8 + 2 * p]);
        B2[p] = pack2(bv.x, bv.y);
    }
    __syncthreads();   // pk ready

    const int xbase = x0 + 4 * q;
    float* obase = out + ((size_t)(b * RHO + c8) * HH + y0) * WW + xbase;
    const size_t plane = (size_t)HH * WW;

    // ---- Stage B: levels-outer, LUT streamed from SMEM (broadcast LDS) ----
#pragma unroll 1
    for (int ty = 0; ty < TY; ty++) {
        uint32_t pv[4];
#pragma unroll
        for (int i = 0; i < 4; i++)
            pv[i] = pk[ty][4 * q + i];

        unsigned long long acc[4][4];   // [pixel][pair]
#pragma unroll
        for (int l = 0; l < 7; l++) {
            unsigned long long Ul[4];
#pragma unroll
            for (int p = 0; p < 4; p++) {
                const float2 uv = *reinterpret_cast<const float2*>(&uS[l][c8 + 2 * p]);
                Ul[p] = pack2(uv.x, uv.y);
            }
#pragma unroll
            for (int i = 0; i < 4; i++) {
                uint32_t bits = ((pv[i] >> (4 * (l + 1))) & 0xFu) | 0x4B000000u;
                unsigned long long md = pack_dup(__uint_as_float(bits) - 8388608.0f);
                if (l == 0) {
#pragma unroll
                    for (int p = 0; p < 4; p++)
                        acc[i][p] = ffma2(md, Ul[p], B2[p]);
                } else {
#pragma unroll
                    for (int p = 0; p < 4; p++)
                        acc[i][p] = ffma2(md, Ul[p], acc[i][p]);
                }
            }
        }

        // ReLU + streaming float4 stores: 512B contiguous per warp per plane-row
        float* orow = obase + (size_t)ty * WW;
#pragma unroll
        for (int p = 0; p < 4; p++) {
            float lo0, hi0, lo1, hi1, lo2, hi2, lo3, hi3;
            unpack2(acc[0][p], lo0, hi0);
            unpack2(acc[1][p], lo1, hi1);
            unpack2(acc[2][p], lo2, hi2);
            unpack2(acc[3][p], lo3, hi3);
            float4 v0 = make_float4(fmaxf(lo0, 0.0f), fmaxf(lo1, 0.0f),
                                    fmaxf(lo2, 0.0f), fmaxf(lo3, 0.0f));
            float4 v1 = make_float4(fmaxf(hi0, 0.0f), fmaxf(hi1, 0.0f),
                                    fmaxf(hi2, 0.0f), fmaxf(hi3, 0.0f));
            __stcs(reinterpret_cast<float4*>(orow + (size_t)(2 * p) * plane), v0);
            __stcs(reinterpret_cast<float4*>(orow + (size_t)(2 * p + 1) * plane), v1);
        }
    }
}

// ---------------------------------------------------------------------------
// Harness entry point
// ---------------------------------------------------------------------------
extern "C" void kernel_launch(void* const* d_in, const int* in_sizes, int n_in,
                              void* d_out, int out_size) {
    const float* x  = (const float*)d_in[0];
    const float* w1 = (const float*)d_in[1];
    const float* b1 = (const float*)d_in[2];
    const float* w2 = (const float*)d_in[3];
    const float* b2 = (const float*)d_in[4];
    const float* w3 = (const float*)d_in[5];
    const float* b3 = (const float*)d_in[6];
    float* out = (float*)d_out;

    dim3 grid(WW / TX, HH / TY, BATCH);   // (3, 48, 8) = 1152 blocks
    dim3 blk(32, 8);
    lpmp_fused<<<grid, blk>>>(x, w1, b1, w2, b2, w3, b3, out);
}